// round 1
// baseline (speedup 1.0000x reference)
#include <cuda_runtime.h>
#include <cuda_bf16.h>

// Problem constants
#define NB   32
#define NN   8400
#define NCLS 80
#define NCF  (NN * NCLS)       // 672000 scores per batch
#define TOPK 1024
#define CAP  8192              // candidate buffer per batch (expected ~3600)
#define NDET 300
#define THRS 0.001f
#define IOUT 0.7f

// ---------------- scratch (device globals; no allocation allowed) ----------
__device__ unsigned int        g_hist[NB * 65536];       // 8 MB
__device__ int                 g_thr[NB];
__device__ int                 g_cnt[NB];
__device__ unsigned long long  g_cand[NB * CAP];         // 2 MB
__device__ float4              g_box[NB * TOPK];         // original boxes of top-1024
__device__ float               g_sc [NB * TOPK];
__device__ int                 g_cls[NB * TOPK];
__device__ unsigned int        g_mask[NB * TOPK * 32];   // 4 MB suppression bitmatrix

// ---------------- kernel 0: zero hist + counters ---------------------------
__global__ void k_zero() {
    int i = blockIdx.x * blockDim.x + threadIdx.x;
    const int total = NB * 65536;
    for (; i < total; i += gridDim.x * blockDim.x) g_hist[i] = 0;
    if (blockIdx.x == 0 && threadIdx.x < NB) g_cnt[threadIdx.x] = 0;
}

// masked key: 0 if score <= 0.001 (matches jnp.where(scores > thr, scores, 0))
__device__ __forceinline__ unsigned maskkey(float s) {
    return (s > THRS) ? __float_as_uint(s) : 0u;
}

// ---------------- kernel 1: 16-bit-prefix histogram -------------------------
__global__ void k_hist(const float* __restrict__ scores) {
    const float4* s4 = (const float4*)scores;
    const int perb = NCF / 4;             // 168000 float4 per batch
    int i = blockIdx.x * blockDim.x + threadIdx.x;
    const int total = NB * perb;
    for (; i < total; i += gridDim.x * blockDim.x) {
        int b = i / perb;
        float4 v = s4[i];
        unsigned base = (unsigned)b << 16;
        atomicAdd(&g_hist[base + (maskkey(v.x) >> 16)], 1u);
        atomicAdd(&g_hist[base + (maskkey(v.y) >> 16)], 1u);
        atomicAdd(&g_hist[base + (maskkey(v.z) >> 16)], 1u);
        atomicAdd(&g_hist[base + (maskkey(v.w) >> 16)], 1u);
    }
}

// ---------------- kernel 2: find 16-bit threshold bin per batch -------------
// T = largest bin value such that count(keys with bin >= T) >= TOPK, bin 0 excluded.
__global__ void k_thresh() {
    __shared__ unsigned coarse[256];
    __shared__ unsigned fine[256];
    __shared__ int sel;
    __shared__ unsigned cumsh;
    int b = blockIdx.x;
    int t = threadIdx.x;
    const unsigned* h = &g_hist[(unsigned)b << 16];

    unsigned s = 0;
    #pragma unroll 8
    for (int f = 0; f < 256; f++) s += h[(t << 8) + f];
    coarse[t] = s;
    __syncthreads();

    if (t == 0) {
        sel = -1;
        unsigned cum = 0;
        unsigned h0 = h[0];
        for (int c = 255; c >= 0; c--) {
            unsigned cc = coarse[c] - (c == 0 ? h0 : 0u);
            if (cum + cc >= TOPK) { sel = c; cumsh = cum; break; }
            cum += cc;
        }
        if (sel < 0) g_thr[b] = 1;   // fewer than TOPK positives (won't happen here)
    }
    __syncthreads();
    int c = sel;
    if (c >= 0) {
        fine[t] = h[(c << 8) + t];
        __syncthreads();
        if (t == 0) {
            unsigned cum = cumsh;
            int T = 1;
            int lo = (c == 0) ? 1 : 0;
            for (int fb = 255; fb >= lo; fb--) {
                cum += fine[fb];
                if (cum >= TOPK) { T = (c << 8) + fb; break; }
            }
            g_thr[b] = T;
        }
    }
}

// ---------------- kernel 3: collect candidates >= threshold -----------------
__global__ void k_collect(const float* __restrict__ scores) {
    const float4* s4 = (const float4*)scores;
    const int perb = NCF / 4;
    int i = blockIdx.x * blockDim.x + threadIdx.x;
    const int total = NB * perb;
    for (; i < total; i += gridDim.x * blockDim.x) {
        int b = i / perb;
        int j0 = (i - b * perb) * 4;
        int T = g_thr[b];
        float4 v = s4[i];
        float vv[4] = {v.x, v.y, v.z, v.w};
        #pragma unroll
        for (int q = 0; q < 4; q++) {
            unsigned key = maskkey(vv[q]);
            if ((int)(key >> 16) >= T) {
                int p = atomicAdd(&g_cnt[b], 1);
                if (p < CAP) {
                    unsigned idx = (unsigned)(j0 + q);
                    g_cand[b * CAP + p] =
                        ((unsigned long long)key << 32) | (unsigned long long)(~idx);
                }
            }
        }
    }
}

// ---------------- kernel 4: per-batch bitonic sort + gather top-1024 --------
// sort key u64 = (score_bits << 32) | ~flat_idx, descending ->
// score desc, flat idx ascending on ties (matches lax.top_k stability)
__global__ void __launch_bounds__(1024) k_sort(const float4* __restrict__ boxes) {
    extern __shared__ unsigned long long sm[];
    int b = blockIdx.x;
    int tid = threadIdx.x;
    int cnt = g_cnt[b];
    if (cnt > CAP) cnt = CAP;
    for (int i = tid; i < CAP; i += 1024)
        sm[i] = (i < cnt) ? g_cand[b * CAP + i] : 0ull;
    __syncthreads();

    for (int k2 = 2; k2 <= CAP; k2 <<= 1) {
        for (int j = k2 >> 1; j > 0; j >>= 1) {
            for (int i = tid; i < CAP; i += 1024) {
                int ixj = i ^ j;
                if (ixj > i) {
                    unsigned long long a = sm[i], c = sm[ixj];
                    bool desc = ((i & k2) == 0);
                    if (desc ? (a < c) : (a > c)) { sm[i] = c; sm[ixj] = a; }
                }
            }
            __syncthreads();
        }
    }

    // each thread emits one of the top-1024
    unsigned long long kk = sm[tid];
    unsigned keyhi = (unsigned)(kk >> 32);
    float4 bx = make_float4(0.f, 0.f, 0.f, 0.f);
    int cls = 0; float sc = 0.f;
    if (keyhi != 0) {
        unsigned idx = ~(unsigned)(kk & 0xFFFFFFFFull);
        int n = (int)(idx / NCLS);
        cls = (int)(idx % NCLS);
        sc = __uint_as_float(keyhi);
        bx = boxes[b * NN + n];
    }
    g_box[b * TOPK + tid] = bx;
    g_cls[b * TOPK + tid] = cls;
    g_sc [b * TOPK + tid] = sc;
}

// ---------------- kernel 5: build suppression bit-matrix ---------------------
// Replicates reference exactly: offset boxes (coords + cls*4096, fp32-rounded),
// areas and IoU on offset coords, strict iou > 0.7, only bits j > i.
// Cross-class IoU is exactly 0 (gap >= 4096-640), so class-equality gate is exact.
__global__ void __launch_bounds__(1024) k_mask() {
    __shared__ float sy1[TOPK], sx1[TOPK], sy2[TOPK], sx2[TOPK], sa[TOPK];
    __shared__ int   scl[TOPK];
    int b = blockIdx.y;
    int t = threadIdx.x;
    {
        float4 bx = g_box[b * TOPK + t];
        int c = g_cls[b * TOPK + t];
        float off = (float)c * 4096.0f;                 // exact in fp32
        float y1 = __fadd_rn(bx.x, off);
        float x1 = __fadd_rn(bx.y, off);
        float y2 = __fadd_rn(bx.z, off);
        float x2 = __fadd_rn(bx.w, off);
        sy1[t] = y1; sx1[t] = x1; sy2[t] = y2; sx2[t] = x2; scl[t] = c;
        sa[t] = __fmul_rn(__fadd_rn(__fsub_rn(x2, x1), 1.0f),
                          __fadd_rn(__fsub_rn(y2, y1), 1.0f));
    }
    __syncthreads();

    int warp = t >> 5, lane = t & 31;
    int rowBase = blockIdx.x * 256 + warp * 8;
    for (int r = 0; r < 8; r++) {
        int i = rowBase + r;
        float iy1 = sy1[i], ix1 = sx1[i], iy2 = sy2[i], ix2 = sx2[i], ia = sa[i];
        int ic = scl[i];
        unsigned bits = 0;
        int jbase = lane << 5;
        if (jbase + 31 > i) {
            #pragma unroll 4
            for (int jj = 0; jj < 32; jj++) {
                int j = jbase + jj;
                if (j > i && scl[j] == ic) {
                    float yy1 = fmaxf(iy1, sy1[j]);
                    float xx1 = fmaxf(ix1, sx1[j]);
                    float yy2 = fminf(iy2, sy2[j]);
                    float xx2 = fminf(ix2, sx2[j]);
                    float w  = fmaxf(0.0f, __fadd_rn(__fsub_rn(xx2, xx1), 1.0f));
                    float hh = fmaxf(0.0f, __fadd_rn(__fsub_rn(yy2, yy1), 1.0f));
                    float inter = __fmul_rn(w, hh);
                    float iou = __fdiv_rn(inter,
                                 __fsub_rn(__fadd_rn(ia, sa[j]), inter));
                    if (iou > IOUT) bits |= (1u << jj);
                }
            }
        }
        g_mask[(b * TOPK + i) * 32 + lane] = bits;
    }
}

// ---------------- kernel 6: sequential NMS sweep + output -------------------
__global__ void __launch_bounds__(1024) k_sweep(float* __restrict__ out) {
    extern __shared__ unsigned smask[];   // TOPK*32 words = 128 KB
    __shared__ unsigned keepw[32];
    __shared__ int kpref[33];
    int b = blockIdx.x;
    int t = threadIdx.x;

    // stage suppression matrix to smem
    const uint4* gm = (const uint4*)&g_mask[b * TOPK * 32];
    uint4* sm4 = (uint4*)smask;
    for (int i = t; i < TOPK * 32 / 4; i += 1024) sm4[i] = gm[i];

    float sc = g_sc[b * TOPK + t];
    unsigned bal = __ballot_sync(0xffffffff, sc > THRS);   // keep0
    if ((t & 31) == 0) keepw[t >> 5] = bal;
    __syncthreads();

    // greedy sweep by warp 0: lane = keep word index
    if (t < 32) {
        unsigned my = keepw[t];
        for (int i = 0; i < TOPK; i++) {
            unsigned kw = __shfl_sync(0xffffffff, my, i >> 5);
            if ((kw >> (i & 31)) & 1u)
                my &= ~smask[i * 32 + t];
        }
        keepw[t] = my;
        int p = __popc(my);
        int x = p;
        #pragma unroll
        for (int o = 1; o < 32; o <<= 1) {
            int y = __shfl_up_sync(0xffffffff, x, o);
            if (t >= o) x += y;
        }
        kpref[t] = x - p;            // exclusive prefix of kept counts
        if (t == 31) kpref[32] = x;  // total kept
    }
    __syncthreads();

    int w = t >> 5, l = t & 31;
    unsigned kw = keepw[w];
    bool kept = (kw >> l) & 1u;
    unsigned lowm = (l == 0) ? 0u : ((1u << l) - 1u);
    int TKall = kpref[32];

    int slot = -1;
    float oscore = 0.0f;
    if (kept) {
        int kr = kpref[w] + __popc(kw & lowm);
        if (kr < NDET) { slot = kr; oscore = sc; }
    } else {
        // top_k over zeros is stable: suppressed/padded positions ascending
        int sr = (w << 5) - kpref[w] + __popc((~kw) & lowm);
        int s2 = TKall + sr;
        if (s2 < NDET) { slot = s2; oscore = 0.0f; }
    }

    // output layout (float32): boxes[32,300,4] | scores[32,300] | labels[32,300] | n_valid[32,1]
    if (slot >= 0) {
        float4 bx = g_box[b * TOPK + t];
        float* ob = out + ((size_t)b * NDET + slot) * 4;
        ob[0] = bx.x; ob[1] = bx.y; ob[2] = bx.z; ob[3] = bx.w;
        out[NB * NDET * 4 + b * NDET + slot] = oscore;
        out[NB * NDET * 5 + b * NDET + slot] = (float)g_cls[b * TOPK + t];
    }
    if (t == 0)
        out[NB * NDET * 6 + b] = (float)(TKall < NDET ? TKall : NDET);
}

// ---------------- launch ----------------------------------------------------
extern "C" void kernel_launch(void* const* d_in, const int* in_sizes, int n_in,
                              void* d_out, int out_size) {
    const float* boxes  = (const float*)d_in[0];
    const float* scores = (const float*)d_in[1];
    if (n_in >= 2 && in_sizes[0] > in_sizes[1]) {  // robust to input ordering
        boxes  = (const float*)d_in[1];
        scores = (const float*)d_in[0];
    }
    float* out = (float*)d_out;

    cudaFuncSetAttribute(k_sort,  cudaFuncAttributeMaxDynamicSharedMemorySize, CAP * 8);
    cudaFuncSetAttribute(k_sweep, cudaFuncAttributeMaxDynamicSharedMemorySize, TOPK * 32 * 4);

    k_zero   <<<512, 256>>>();
    k_hist   <<<2048, 256>>>(scores);
    k_thresh <<<NB, 256>>>();
    k_collect<<<2048, 256>>>(scores);
    k_sort   <<<NB, 1024, CAP * 8>>>((const float4*)boxes);
    k_mask   <<<dim3(4, NB), 1024>>>();
    k_sweep  <<<NB, 1024, TOPK * 32 * 4>>>(out);
}

// round 2
// speedup vs baseline: 1.8224x; 1.8224x over previous
#include <cuda_runtime.h>
#include <cuda_bf16.h>

// Problem constants
#define NB   32
#define NN   8400
#define NCLS 80
#define NCF  (NN * NCLS)       // 672000 scores per batch
#define TOPK 1024
#define CAP  8192              // candidate buffer per batch (expected ~3600)
#define NDET 300
#define THRS 0.001f
#define IOUT 0.7f

#define HSLICES 4              // private histograms per batch
#define HWORDS  32768          // 65536 bins packed as u16 pairs

// ---------------- scratch (device globals; no allocation allowed) ----------
__device__ unsigned int        g_histp[NB * HSLICES * HWORDS];  // 16 MB
__device__ int                 g_thr[NB];
__device__ int                 g_cnt[NB];
__device__ unsigned long long  g_cand[NB * CAP];                // 2 MB
__device__ float4              g_box[NB * TOPK];
__device__ float               g_sc [NB * TOPK];
__device__ int                 g_cls[NB * TOPK];
__device__ unsigned int        g_mask[NB * TOPK * 32];          // 4 MB

// masked key: 0 if score <= 0.001 (matches jnp.where(scores > thr, scores, 0))
__device__ __forceinline__ unsigned maskkey(float s) {
    return (s > THRS) ? __float_as_uint(s) : 0u;
}

// ---------------- kernel 1: privatized 16-bit-prefix histogram -------------
// grid (HSLICES, NB), 1024 threads, 128 KB smem. No global atomics.
__global__ void __launch_bounds__(1024) k_hist(const float4* __restrict__ s4) {
    extern __shared__ unsigned sh[];                 // HWORDS u32 (u16 pairs)
    const int b = blockIdx.y, s = blockIdx.x, t = threadIdx.x;
    for (int i = t; i < HWORDS; i += 1024) sh[i] = 0;
    __syncthreads();

    const int perb4  = NCF / 4;                      // 168000
    const int slice  = perb4 / HSLICES;              // 42000
    const float4* src = s4 + (size_t)b * perb4 + (size_t)s * slice;
    for (int i = t; i < slice; i += 1024) {
        float4 v = src[i];
        unsigned k0 = maskkey(v.x) >> 16;
        unsigned k1 = maskkey(v.y) >> 16;
        unsigned k2 = maskkey(v.z) >> 16;
        unsigned k3 = maskkey(v.w) >> 16;
        atomicAdd(&sh[k0 >> 1], 1u << ((k0 & 1) * 16));
        atomicAdd(&sh[k1 >> 1], 1u << ((k1 & 1) * 16));
        atomicAdd(&sh[k2 >> 1], 1u << ((k2 & 1) * 16));
        atomicAdd(&sh[k3 >> 1], 1u << ((k3 & 1) * 16));
    }
    __syncthreads();

    unsigned* dst = g_histp + ((size_t)(b * HSLICES + s) << 15);
    for (int i = t; i < HWORDS; i += 1024) dst[i] = sh[i];
}

// ---------------- kernel 2: merge + find 16-bit threshold per batch ---------
// T = largest bin such that count(keys with bin >= T) >= TOPK, bin 0 excluded.
__global__ void __launch_bounds__(1024) k_thresh() {
    extern __shared__ unsigned merged[];             // HWORDS u32
    __shared__ unsigned partial[1024];
    __shared__ unsigned coarse[256];
    __shared__ int sel;
    __shared__ unsigned cumsh;
    const int b = blockIdx.x, t = threadIdx.x;
    if (t == 0) g_cnt[b] = 0;                        // reset collector counter

    const unsigned* p = g_histp + ((size_t)b * HSLICES << 15);
    unsigned csum = 0;
    #pragma unroll
    for (int k = 0; k < 32; k++) {
        int w = t * 32 + k;
        unsigned m = p[w] + p[HWORDS + w] + p[2 * HWORDS + w] + p[3 * HWORDS + w];
        merged[w] = m;
        csum += (m & 0xFFFFu) + (m >> 16);
    }
    partial[t] = csum;
    __syncthreads();
    if (t < 256)
        coarse[t] = partial[4 * t] + partial[4 * t + 1] +
                    partial[4 * t + 2] + partial[4 * t + 3];
    __syncthreads();

    if (t == 0) {
        sel = -1;
        unsigned cum = 0;
        unsigned h0 = merged[0] & 0xFFFFu;           // bin 0 (masked scores)
        for (int c = 255; c >= 0; c--) {
            unsigned cc = coarse[c] - (c == 0 ? h0 : 0u);
            if (cum + cc >= TOPK) { sel = c; cumsh = cum; break; }
            cum += cc;
        }
        if (sel < 0) g_thr[b] = 1;                   // fewer than TOPK positives
    }
    __syncthreads();
    if (t == 0 && sel >= 0) {
        unsigned cum = cumsh;
        int T = 1;
        int lo = (sel == 0) ? 1 : 0;
        for (int fb = 255; fb >= lo; fb--) {
            int bin = (sel << 8) + fb;
            unsigned m = merged[bin >> 1];
            unsigned cc = (bin & 1) ? (m >> 16) : (m & 0xFFFFu);
            cum += cc;
            if (cum >= TOPK) { T = bin; break; }
        }
        g_thr[b] = T;
    }
}

// ---------------- kernel 3: collect candidates >= threshold -----------------
// grid (82, NB), 256 threads. No division; unrolled for MLP.
__global__ void k_collect(const float4* __restrict__ s4) {
    const int b = blockIdx.y;
    const int perb4 = NCF / 4;
    const int T = g_thr[b];
    const float4* src = s4 + (size_t)b * perb4;
    const int stride = gridDim.x * blockDim.x;
    int i = blockIdx.x * blockDim.x + threadIdx.x;
    #pragma unroll 4
    for (; i < perb4; i += stride) {
        float4 v = src[i];
        float vv[4] = {v.x, v.y, v.z, v.w};
        #pragma unroll
        for (int q = 0; q < 4; q++) {
            unsigned key = maskkey(vv[q]);
            if ((int)(key >> 16) >= T) {
                int p = atomicAdd(&g_cnt[b], 1);
                if (p < CAP) {
                    unsigned idx = (unsigned)(i * 4 + q);
                    g_cand[b * CAP + p] =
                        ((unsigned long long)key << 32) | (unsigned long long)(~idx);
                }
            }
        }
    }
}

// ---------------- kernel 4: per-batch bitonic sort + gather top-1024 --------
// sort key u64 = (score_bits << 32) | ~flat_idx, descending ->
// score desc, flat idx ascending on ties (matches lax.top_k stability)
__global__ void __launch_bounds__(1024) k_sort(const float4* __restrict__ boxes) {
    extern __shared__ unsigned long long sm[];
    int b = blockIdx.x;
    int tid = threadIdx.x;
    int cnt = g_cnt[b];
    if (cnt > CAP) cnt = CAP;
    for (int i = tid; i < CAP; i += 1024)
        sm[i] = (i < cnt) ? g_cand[b * CAP + i] : 0ull;
    __syncthreads();

    for (int k2 = 2; k2 <= CAP; k2 <<= 1) {
        for (int j = k2 >> 1; j > 0; j >>= 1) {
            for (int i = tid; i < CAP; i += 1024) {
                int ixj = i ^ j;
                if (ixj > i) {
                    unsigned long long a = sm[i], c = sm[ixj];
                    bool desc = ((i & k2) == 0);
                    if (desc ? (a < c) : (a > c)) { sm[i] = c; sm[ixj] = a; }
                }
            }
            __syncthreads();
        }
    }

    unsigned long long kk = sm[tid];
    unsigned keyhi = (unsigned)(kk >> 32);
    float4 bx = make_float4(0.f, 0.f, 0.f, 0.f);
    int cls = 0; float sc = 0.f;
    if (keyhi != 0) {
        unsigned idx = ~(unsigned)(kk & 0xFFFFFFFFull);
        int n = (int)(idx / NCLS);
        cls = (int)(idx % NCLS);
        sc = __uint_as_float(keyhi);
        bx = boxes[b * NN + n];
    }
    g_box[b * TOPK + tid] = bx;
    g_cls[b * TOPK + tid] = cls;
    g_sc [b * TOPK + tid] = sc;
}

// ---------------- kernel 5: build suppression bit-matrix ---------------------
// Bit-exact vs reference: offset boxes (coords + cls*4096, fp32-rounded),
// areas and IoU on offset coords, strict iou > 0.7, only bits j > i.
__global__ void __launch_bounds__(1024) k_mask() {
    __shared__ float sy1[TOPK], sx1[TOPK], sy2[TOPK], sx2[TOPK], sa[TOPK];
    __shared__ int   scl[TOPK];
    int b = blockIdx.y;
    int t = threadIdx.x;
    {
        float4 bx = g_box[b * TOPK + t];
        int c = g_cls[b * TOPK + t];
        float off = (float)c * 4096.0f;
        float y1 = __fadd_rn(bx.x, off);
        float x1 = __fadd_rn(bx.y, off);
        float y2 = __fadd_rn(bx.z, off);
        float x2 = __fadd_rn(bx.w, off);
        sy1[t] = y1; sx1[t] = x1; sy2[t] = y2; sx2[t] = x2; scl[t] = c;
        sa[t] = __fmul_rn(__fadd_rn(__fsub_rn(x2, x1), 1.0f),
                          __fadd_rn(__fsub_rn(y2, y1), 1.0f));
    }
    __syncthreads();

    int warp = t >> 5, lane = t & 31;
    int rowBase = blockIdx.x * 256 + warp * 8;
    for (int r = 0; r < 8; r++) {
        int i = rowBase + r;
        float iy1 = sy1[i], ix1 = sx1[i], iy2 = sy2[i], ix2 = sx2[i], ia = sa[i];
        int ic = scl[i];
        unsigned bits = 0;
        int jbase = lane << 5;
        if (jbase + 31 > i) {
            #pragma unroll 4
            for (int jj = 0; jj < 32; jj++) {
                int j = jbase + jj;
                if (j > i && scl[j] == ic) {
                    float yy1 = fmaxf(iy1, sy1[j]);
                    float xx1 = fmaxf(ix1, sx1[j]);
                    float yy2 = fminf(iy2, sy2[j]);
                    float xx2 = fminf(ix2, sx2[j]);
                    float w  = fmaxf(0.0f, __fadd_rn(__fsub_rn(xx2, xx1), 1.0f));
                    float hh = fmaxf(0.0f, __fadd_rn(__fsub_rn(yy2, yy1), 1.0f));
                    float inter = __fmul_rn(w, hh);
                    float iou = __fdiv_rn(inter,
                                 __fsub_rn(__fadd_rn(ia, sa[j]), inter));
                    if (iou > IOUT) bits |= (1u << jj);
                }
            }
        }
        g_mask[(b * TOPK + i) * 32 + lane] = bits;
    }
}

// ---------------- kernel 6: sequential NMS sweep + output -------------------
__global__ void __launch_bounds__(1024) k_sweep(float* __restrict__ out) {
    extern __shared__ unsigned smask[];   // TOPK*32 words = 128 KB
    __shared__ unsigned keepw[32];
    __shared__ int kpref[33];
    int b = blockIdx.x;
    int t = threadIdx.x;

    const uint4* gm = (const uint4*)&g_mask[b * TOPK * 32];
    uint4* sm4 = (uint4*)smask;
    for (int i = t; i < TOPK * 32 / 4; i += 1024) sm4[i] = gm[i];

    float sc = g_sc[b * TOPK + t];
    unsigned bal = __ballot_sync(0xffffffff, sc > THRS);   // keep0
    if ((t & 31) == 0) keepw[t >> 5] = bal;
    __syncthreads();

    if (t < 32) {
        unsigned my = keepw[t];
        for (int i = 0; i < TOPK; i++) {
            unsigned kw = __shfl_sync(0xffffffff, my, i >> 5);
            if ((kw >> (i & 31)) & 1u)
                my &= ~smask[i * 32 + t];
        }
        keepw[t] = my;
        int p = __popc(my);
        int x = p;
        #pragma unroll
        for (int o = 1; o < 32; o <<= 1) {
            int y = __shfl_up_sync(0xffffffff, x, o);
            if (t >= o) x += y;
        }
        kpref[t] = x - p;
        if (t == 31) kpref[32] = x;
    }
    __syncthreads();

    int w = t >> 5, l = t & 31;
    unsigned kw = keepw[w];
    bool kept = (kw >> l) & 1u;
    unsigned lowm = (l == 0) ? 0u : ((1u << l) - 1u);
    int TKall = kpref[32];

    int slot = -1;
    float oscore = 0.0f;
    if (kept) {
        int kr = kpref[w] + __popc(kw & lowm);
        if (kr < NDET) { slot = kr; oscore = sc; }
    } else {
        int sr = (w << 5) - kpref[w] + __popc((~kw) & lowm);
        int s2 = TKall + sr;
        if (s2 < NDET) { slot = s2; oscore = 0.0f; }
    }

    // output layout (float32): boxes[32,300,4] | scores[32,300] | labels[32,300] | n_valid[32,1]
    if (slot >= 0) {
        float4 bx = g_box[b * TOPK + t];
        float* ob = out + ((size_t)b * NDET + slot) * 4;
        ob[0] = bx.x; ob[1] = bx.y; ob[2] = bx.z; ob[3] = bx.w;
        out[NB * NDET * 4 + b * NDET + slot] = oscore;
        out[NB * NDET * 5 + b * NDET + slot] = (float)g_cls[b * TOPK + t];
    }
    if (t == 0)
        out[NB * NDET * 6 + b] = (float)(TKall < NDET ? TKall : NDET);
}

// ---------------- launch ----------------------------------------------------
extern "C" void kernel_launch(void* const* d_in, const int* in_sizes, int n_in,
                              void* d_out, int out_size) {
    const float* boxes  = (const float*)d_in[0];
    const float* scores = (const float*)d_in[1];
    if (n_in >= 2 && in_sizes[0] > in_sizes[1]) {
        boxes  = (const float*)d_in[1];
        scores = (const float*)d_in[0];
    }
    float* out = (float*)d_out;

    cudaFuncSetAttribute(k_hist,   cudaFuncAttributeMaxDynamicSharedMemorySize, HWORDS * 4);
    cudaFuncSetAttribute(k_thresh, cudaFuncAttributeMaxDynamicSharedMemorySize, HWORDS * 4);
    cudaFuncSetAttribute(k_sort,   cudaFuncAttributeMaxDynamicSharedMemorySize, CAP * 8);
    cudaFuncSetAttribute(k_sweep,  cudaFuncAttributeMaxDynamicSharedMemorySize, TOPK * 32 * 4);

    k_hist   <<<dim3(HSLICES, NB), 1024, HWORDS * 4>>>((const float4*)scores);
    k_thresh <<<NB, 1024, HWORDS * 4>>>();
    k_collect<<<dim3(82, NB), 256>>>((const float4*)scores);
    k_sort   <<<NB, 1024, CAP * 8>>>((const float4*)boxes);
    k_mask   <<<dim3(4, NB), 1024>>>();
    k_sweep  <<<NB, 1024, TOPK * 32 * 4>>>(out);
}

// round 3
// speedup vs baseline: 2.1443x; 1.1766x over previous
#include <cuda_runtime.h>
#include <cuda_bf16.h>

// Problem constants
#define NB   32
#define NN   8400
#define NCLS 80
#define NCF  (NN * NCLS)       // 672000 scores per batch
#define TOPK 1024
#define CAP  8192              // candidate buffer per batch (expected ~1040)
#define NDET 300
#define THRS 0.001f
#define IOUT 0.7f

#define HSLICES 4              // private histograms per batch
#define HWORDS  32768          // 65536 bins packed as u16 pairs

// ---------------- scratch (device globals; no allocation allowed) ----------
__device__ unsigned int        g_histp[NB * HSLICES * HWORDS];  // 16 MB
__device__ int                 g_thr[NB];
__device__ int                 g_cnt[NB];
__device__ unsigned long long  g_cand[NB * CAP];                // 2 MB
__device__ float4              g_box[NB * TOPK];
__device__ float               g_sc [NB * TOPK];
__device__ int                 g_cls[NB * TOPK];

// Monotonic selection bin: trunc(s*65536), 0 for masked scores.
// (Only used for thresholding; exact float bits remain the sort key.)
__device__ __forceinline__ unsigned binof(float s) {
    if (!(s > THRS)) return 0u;
    unsigned b = (unsigned)(s * 65536.0f);
    return b > 65535u ? 65535u : b;
}

// ---------------- kernel 1: privatized value-scaled histogram --------------
// grid (HSLICES, NB), 1024 threads, 128 KB smem. Conflict-free atomics.
__global__ void __launch_bounds__(1024) k_hist(const float4* __restrict__ s4) {
    extern __shared__ unsigned sh[];                 // HWORDS u32 (u16 pairs)
    const int b = blockIdx.y, s = blockIdx.x, t = threadIdx.x;
    for (int i = t; i < HWORDS; i += 1024) sh[i] = 0;
    __syncthreads();

    const int perb4  = NCF / 4;                      // 168000
    const int slice  = perb4 / HSLICES;              // 42000
    const float4* src = s4 + (size_t)b * perb4 + (size_t)s * slice;
    for (int i = t; i < slice; i += 1024) {
        float4 v = src[i];
        unsigned k0 = binof(v.x);
        unsigned k1 = binof(v.y);
        unsigned k2 = binof(v.z);
        unsigned k3 = binof(v.w);
        atomicAdd(&sh[k0 >> 1], 1u << ((k0 & 1) * 16));
        atomicAdd(&sh[k1 >> 1], 1u << ((k1 & 1) * 16));
        atomicAdd(&sh[k2 >> 1], 1u << ((k2 & 1) * 16));
        atomicAdd(&sh[k3 >> 1], 1u << ((k3 & 1) * 16));
    }
    __syncthreads();

    unsigned* dst = g_histp + ((size_t)(b * HSLICES + s) << 15);
    for (int i = t; i < HWORDS; i += 1024) dst[i] = sh[i];
}

// ---------------- kernel 2: merge + find threshold bin per batch ------------
// T = largest bin >= 1 such that count(bins >= T) >= TOPK.
__global__ void __launch_bounds__(1024) k_thresh() {
    extern __shared__ unsigned merged[];             // HWORDS u32
    __shared__ unsigned partial[1024];
    __shared__ unsigned coarse[256];
    __shared__ int sel;
    __shared__ unsigned cumsh;
    const int b = blockIdx.x, t = threadIdx.x;
    if (t == 0) g_cnt[b] = 0;                        // reset collector counter

    const unsigned* p = g_histp + ((size_t)b * HSLICES << 15);
    unsigned csum = 0;
    #pragma unroll
    for (int k = 0; k < 32; k++) {
        int w = t * 32 + k;
        unsigned m = p[w] + p[HWORDS + w] + p[2 * HWORDS + w] + p[3 * HWORDS + w];
        merged[w] = m;
        csum += (m & 0xFFFFu) + (m >> 16);
    }
    partial[t] = csum;
    __syncthreads();
    if (t < 256)
        coarse[t] = partial[4 * t] + partial[4 * t + 1] +
                    partial[4 * t + 2] + partial[4 * t + 3];
    __syncthreads();

    if (t == 0) {
        sel = -1;
        unsigned cum = 0;
        unsigned h0 = merged[0] & 0xFFFFu;           // bin 0 (masked scores)
        for (int c = 255; c >= 0; c--) {
            unsigned cc = coarse[c] - (c == 0 ? h0 : 0u);
            if (cum + cc >= TOPK) { sel = c; cumsh = cum; break; }
            cum += cc;
        }
        if (sel < 0) g_thr[b] = 1;                   // fewer than TOPK positives
        else {
            unsigned cum2 = cumsh;
            int T = 1;
            int lo = (sel == 0) ? 1 : 0;
            for (int fb = 255; fb >= lo; fb--) {
                int bin = (sel << 8) + fb;
                unsigned m = merged[bin >> 1];
                unsigned cc = (bin & 1) ? (m >> 16) : (m & 0xFFFFu);
                cum2 += cc;
                if (cum2 >= TOPK) { T = bin; break; }
            }
            g_thr[b] = T;
        }
    }
}

// ---------------- kernel 3: collect candidates with bin >= T ----------------
__global__ void k_collect(const float4* __restrict__ s4) {
    const int b = blockIdx.y;
    const int perb4 = NCF / 4;
    const unsigned T = (unsigned)g_thr[b];
    const float4* src = s4 + (size_t)b * perb4;
    const int stride = gridDim.x * blockDim.x;
    int i = blockIdx.x * blockDim.x + threadIdx.x;
    #pragma unroll 4
    for (; i < perb4; i += stride) {
        float4 v = src[i];
        float vv[4] = {v.x, v.y, v.z, v.w};
        #pragma unroll
        for (int q = 0; q < 4; q++) {
            if (binof(vv[q]) >= T) {
                int p = atomicAdd(&g_cnt[b], 1);
                if (p < CAP) {
                    unsigned idx = (unsigned)(i * 4 + q);
                    unsigned key = __float_as_uint(vv[q]);
                    g_cand[b * CAP + p] =
                        ((unsigned long long)key << 32) | (unsigned long long)(~idx);
                }
            }
        }
    }
}

// ---------------- kernel 4: per-batch bitonic sort (dynamic n) + gather -----
// sort key u64 = (float_bits << 32) | ~flat_idx, descending ->
// score desc, flat idx ascending on ties (matches lax.top_k stability)
__global__ void __launch_bounds__(1024) k_sort(const float4* __restrict__ boxes) {
    extern __shared__ unsigned long long sm[];
    int b = blockIdx.x;
    int tid = threadIdx.x;
    int cnt = g_cnt[b];
    if (cnt > CAP) cnt = CAP;
    int n2 = 2048;
    while (n2 < cnt) n2 <<= 1;                       // <= CAP
    for (int i = tid; i < n2; i += 1024)
        sm[i] = (i < cnt) ? g_cand[b * CAP + i] : 0ull;
    __syncthreads();

    for (int k2 = 2; k2 <= n2; k2 <<= 1) {
        for (int j = k2 >> 1; j > 0; j >>= 1) {
            for (int i = tid; i < n2; i += 1024) {
                int ixj = i ^ j;
                if (ixj > i) {
                    unsigned long long a = sm[i], c = sm[ixj];
                    bool desc = ((i & k2) == 0);
                    if (desc ? (a < c) : (a > c)) { sm[i] = c; sm[ixj] = a; }
                }
            }
            __syncthreads();
        }
    }

    unsigned long long kk = sm[tid];
    unsigned keyhi = (unsigned)(kk >> 32);
    float4 bx = make_float4(0.f, 0.f, 0.f, 0.f);
    int cls = 0; float sc = 0.f;
    if (keyhi != 0) {
        unsigned idx = ~(unsigned)(kk & 0xFFFFFFFFull);
        int n = (int)(idx / NCLS);
        cls = (int)(idx % NCLS);
        sc = __uint_as_float(keyhi);
        bx = boxes[b * NN + n];
    }
    g_box[b * TOPK + tid] = bx;
    g_cls[b * TOPK + tid] = cls;
    g_sc [b * TOPK + tid] = sc;
}

// rotate-swizzled mask slot: row i, col-word w (conflict-free store AND load)
__device__ __forceinline__ int midx(int i, int w) {
    return (i << 5) + ((w + i) & 31);
}

// ---------------- kernel 5: fused mask build + sequential sweep + output ----
// Bit-exact vs reference: offset boxes (coords + cls*4096, fp32-rounded),
// IoU on offset coords, strict iou > 0.7, suppression only for j > i.
__global__ void __launch_bounds__(1024) k_nms(float* __restrict__ out) {
    extern __shared__ unsigned smask[];              // TOPK*32 words = 128 KB
    __shared__ float sy1[TOPK], sx1[TOPK], sy2[TOPK], sx2[TOPK], sa[TOPK];
    __shared__ int   scl[TOPK];
    __shared__ unsigned keepw[32];
    __shared__ int kpref[33];
    int b = blockIdx.x;
    int t = threadIdx.x;

    float sc = g_sc[b * TOPK + t];
    {
        float4 bx = g_box[b * TOPK + t];
        int c = g_cls[b * TOPK + t];
        float off = (float)c * 4096.0f;              // exact in fp32
        float y1 = __fadd_rn(bx.x, off);
        float x1 = __fadd_rn(bx.y, off);
        float y2 = __fadd_rn(bx.z, off);
        float x2 = __fadd_rn(bx.w, off);
        sy1[t] = y1; sx1[t] = x1; sy2[t] = y2; sx2[t] = x2; scl[t] = c;
        sa[t] = __fmul_rn(__fadd_rn(__fsub_rn(x2, x1), 1.0f),
                          __fadd_rn(__fsub_rn(y2, y1), 1.0f));
    }
    unsigned bal = __ballot_sync(0xffffffff, sc > THRS);   // keep0
    if ((t & 31) == 0) keepw[t >> 5] = bal;
    __syncthreads();

    // build row t of the suppression matrix (scl[j] reads are broadcasts)
    {
        float iy1 = sy1[t], ix1 = sx1[t], iy2 = sy2[t], ix2 = sx2[t], ia = sa[t];
        int ic = scl[t];
        #pragma unroll 1
        for (int w = 0; w < 32; w++) {
            unsigned bits = 0;
            int jb = w << 5;
            if (jb + 31 > t) {
                #pragma unroll 4
                for (int jj = 0; jj < 32; jj++) {
                    int j = jb + jj;
                    if (j > t && scl[j] == ic) {
                        float yy1 = fmaxf(iy1, sy1[j]);
                        float xx1 = fmaxf(ix1, sx1[j]);
                        float yy2 = fminf(iy2, sy2[j]);
                        float xx2 = fminf(ix2, sx2[j]);
                        float ww = fmaxf(0.0f, __fadd_rn(__fsub_rn(xx2, xx1), 1.0f));
                        float hh = fmaxf(0.0f, __fadd_rn(__fsub_rn(yy2, yy1), 1.0f));
                        float inter = __fmul_rn(ww, hh);
                        float iou = __fdiv_rn(inter,
                                     __fsub_rn(__fadd_rn(ia, sa[j]), inter));
                        if (iou > IOUT) bits |= (1u << jj);
                    }
                }
            }
            smask[midx(t, w)] = bits;
        }
    }
    __syncthreads();

    // greedy sweep by warp 0: lane = keep word index
    if (t < 32) {
        unsigned my = keepw[t];
        for (int i = 0; i < TOPK; i++) {
            unsigned kw = __shfl_sync(0xffffffff, my, i >> 5);
            if ((kw >> (i & 31)) & 1u)
                my &= ~smask[midx(i, t)];
        }
        keepw[t] = my;
        int p = __popc(my);
        int x = p;
        #pragma unroll
        for (int o = 1; o < 32; o <<= 1) {
            int y = __shfl_up_sync(0xffffffff, x, o);
            if (t >= o) x += y;
        }
        kpref[t] = x - p;
        if (t == 31) kpref[32] = x;
    }
    __syncthreads();

    int w = t >> 5, l = t & 31;
    unsigned kw = keepw[w];
    bool kept = (kw >> l) & 1u;
    unsigned lowm = (l == 0) ? 0u : ((1u << l) - 1u);
    int TKall = kpref[32];

    int slot = -1;
    float oscore = 0.0f;
    if (kept) {
        int kr = kpref[w] + __popc(kw & lowm);
        if (kr < NDET) { slot = kr; oscore = sc; }
    } else {
        // top_k over zeros is stable: suppressed/padded positions ascending
        int sr = (w << 5) - kpref[w] + __popc((~kw) & lowm);
        int s2 = TKall + sr;
        if (s2 < NDET) { slot = s2; oscore = 0.0f; }
    }

    // output layout (float32): boxes[32,300,4] | scores[32,300] | labels[32,300] | n_valid[32,1]
    if (slot >= 0) {
        float4 bx = g_box[b * TOPK + t];
        float* ob = out + ((size_t)b * NDET + slot) * 4;
        ob[0] = bx.x; ob[1] = bx.y; ob[2] = bx.z; ob[3] = bx.w;
        out[NB * NDET * 4 + b * NDET + slot] = oscore;
        out[NB * NDET * 5 + b * NDET + slot] = (float)g_cls[b * TOPK + t];
    }
    if (t == 0)
        out[NB * NDET * 6 + b] = (float)(TKall < NDET ? TKall : NDET);
}

// ---------------- launch ----------------------------------------------------
extern "C" void kernel_launch(void* const* d_in, const int* in_sizes, int n_in,
                              void* d_out, int out_size) {
    const float* boxes  = (const float*)d_in[0];
    const float* scores = (const float*)d_in[1];
    if (n_in >= 2 && in_sizes[0] > in_sizes[1]) {
        boxes  = (const float*)d_in[1];
        scores = (const float*)d_in[0];
    }
    float* out = (float*)d_out;

    cudaFuncSetAttribute(k_hist,   cudaFuncAttributeMaxDynamicSharedMemorySize, HWORDS * 4);
    cudaFuncSetAttribute(k_thresh, cudaFuncAttributeMaxDynamicSharedMemorySize, HWORDS * 4);
    cudaFuncSetAttribute(k_sort,   cudaFuncAttributeMaxDynamicSharedMemorySize, CAP * 8);
    cudaFuncSetAttribute(k_nms,    cudaFuncAttributeMaxDynamicSharedMemorySize, TOPK * 32 * 4);

    k_hist   <<<dim3(HSLICES, NB), 1024, HWORDS * 4>>>((const float4*)scores);
    k_thresh <<<NB, 1024, HWORDS * 4>>>();
    k_collect<<<dim3(82, NB), 256>>>((const float4*)scores);
    k_sort   <<<NB, 1024, CAP * 8>>>((const float4*)boxes);
    k_nms    <<<NB, 1024, TOPK * 32 * 4>>>(out);
}

// round 4
// speedup vs baseline: 2.7222x; 1.2695x over previous
#include <cuda_runtime.h>
#include <cuda_bf16.h>

// Problem constants
#define NB   32
#define NN   8400
#define NCLS 80
#define NCF  (NN * NCLS)       // 672000 scores per batch
#define TOPK 1024
#define CAP  8192
#define NDET 300
#define THRS 0.001f
#define IOUT 0.7f

#define CLO   0.96875f         // high-region lower bound (31/32, exact fp32)
#define HSCAL 2097152.0f       // 2^21: (s-CLO)*2^21 in (0, 65536]

#define HSLICES 4
#define HWORDS  32768          // 65536 bins packed as u16 pairs

// ---------------- scratch (device globals; no allocation allowed) ----------
__device__ unsigned int        g_histp[NB * HSLICES * HWORDS];  // 16 MB
__device__ unsigned int        g_coarse[NB * 256];              // zeroed after use
__device__ int                 g_thr[NB];
__device__ int                 g_mode[NB];                      // 1 = high-region bins
__device__ int                 g_cnt[NB];
__device__ unsigned long long  g_cand[NB * CAP];
__device__ float4              g_box[NB * TOPK];
__device__ float               g_sc [NB * TOPK];
__device__ int                 g_cls[NB * TOPK];

// high-region bin (valid only when s > CLO): monotonic in s
__device__ __forceinline__ unsigned binhi(float s) {
    float d = __fsub_rn(s, CLO);
    unsigned b = (unsigned)(__fmul_rn(d, HSCAL));
    return b > 65535u ? 65535u : b;
}
// full-range bin (fallback mode): 0 for masked scores
__device__ __forceinline__ unsigned binlo(float s) {
    if (!(s > THRS)) return 0u;
    unsigned b = (unsigned)(s * 65536.0f);
    return b > 65535u ? 65535u : b;
}

// ---------------- kernel 1: high-region privatized histogram ----------------
// grid (HSLICES, NB), 1024 threads, 128 KB smem. ~1/32 of scores hit atomics.
__global__ void __launch_bounds__(1024) k_hist(const float4* __restrict__ s4) {
    extern __shared__ unsigned sh[];
    const int b = blockIdx.y, s = blockIdx.x, t = threadIdx.x;
    for (int i = t; i < HWORDS; i += 1024) sh[i] = 0;
    __syncthreads();

    const int perb4 = NCF / 4;                        // 168000
    const int slice = perb4 / HSLICES;                // 42000
    const float4* src = s4 + (size_t)b * perb4 + (size_t)s * slice;
    #pragma unroll 4
    for (int i = t; i < slice; i += 1024) {
        float4 v = src[i];
        if (v.x > CLO) { unsigned k = binhi(v.x); atomicAdd(&sh[k >> 1], 1u << ((k & 1) * 16)); }
        if (v.y > CLO) { unsigned k = binhi(v.y); atomicAdd(&sh[k >> 1], 1u << ((k & 1) * 16)); }
        if (v.z > CLO) { unsigned k = binhi(v.z); atomicAdd(&sh[k >> 1], 1u << ((k & 1) * 16)); }
        if (v.w > CLO) { unsigned k = binhi(v.w); atomicAdd(&sh[k >> 1], 1u << ((k & 1) * 16)); }
    }
    __syncthreads();

    // coarse chunk sums (256 chunks of 256 bins = 128 words each)
    if (t < 256) {
        unsigned sum = 0;
        #pragma unroll 8
        for (int k = 0; k < 128; k++) {
            unsigned m = sh[t * 128 + k];
            sum += (m & 0xFFFFu) + (m >> 16);
        }
        if (sum) atomicAdd(&g_coarse[b * 256 + t], sum);
    }
    unsigned* dst = g_histp + ((size_t)(b * HSLICES + s) << 15);
    for (int i = t; i < HWORDS; i += 1024) dst[i] = sh[i];
}

// ---------------- kernel 2: threshold from coarse + one fine chunk ----------
__global__ void __launch_bounds__(256) k_thresh() {
    __shared__ unsigned co[256];
    __shared__ unsigned fine2[256];
    __shared__ int sel;
    __shared__ unsigned cumsh;
    const int b = blockIdx.x, t = threadIdx.x;
    if (t == 0) g_cnt[b] = 0;
    co[t] = g_coarse[b * 256 + t];
    __syncthreads();

    if (t == 0) {
        sel = -1;
        unsigned cum = 0;
        for (int c = 255; c >= 0; c--) {
            if (cum + co[c] >= TOPK) { sel = c; cumsh = cum; break; }
            cum += co[c];
        }
        if (sel < 0) g_mode[b] = 0;                   // fallback to full-range
    }
    __syncthreads();
    int c = sel;
    if (c >= 0) {
        if (t < 128) {
            const unsigned* p = g_histp + ((size_t)b * HSLICES << 15) + c * 128 + t;
            unsigned m = p[0] + p[HWORDS] + p[2 * HWORDS] + p[3 * HWORDS];
            fine2[2 * t]     = m & 0xFFFFu;
            fine2[2 * t + 1] = m >> 16;
        }
        __syncthreads();
        if (t == 0) {
            unsigned cum = cumsh;
            int T = 0;
            for (int fb = 255; fb >= 0; fb--) {
                cum += fine2[fb];
                if (cum >= TOPK) { T = (c << 8) + fb; break; }
            }
            g_thr[b] = T;
            g_mode[b] = 1;
        }
    }
    // zero coarse for next graph replay
    g_coarse[b * 256 + t] = 0;
}

// ---------------- fallback kernels (cold; gated on g_mode[b]==0) ------------
__global__ void __launch_bounds__(1024) k_histlo(const float4* __restrict__ s4) {
    const int b = blockIdx.y;
    if (((volatile int*)g_mode)[b] != 0) return;
    extern __shared__ unsigned sh[];
    const int s = blockIdx.x, t = threadIdx.x;
    for (int i = t; i < HWORDS; i += 1024) sh[i] = 0;
    __syncthreads();
    const int perb4 = NCF / 4;
    const int slice = perb4 / HSLICES;
    const float4* src = s4 + (size_t)b * perb4 + (size_t)s * slice;
    for (int i = t; i < slice; i += 1024) {
        float4 v = src[i];
        unsigned k0 = binlo(v.x), k1 = binlo(v.y), k2 = binlo(v.z), k3 = binlo(v.w);
        atomicAdd(&sh[k0 >> 1], 1u << ((k0 & 1) * 16));
        atomicAdd(&sh[k1 >> 1], 1u << ((k1 & 1) * 16));
        atomicAdd(&sh[k2 >> 1], 1u << ((k2 & 1) * 16));
        atomicAdd(&sh[k3 >> 1], 1u << ((k3 & 1) * 16));
    }
    __syncthreads();
    unsigned* dst = g_histp + ((size_t)(b * HSLICES + s) << 15);
    for (int i = t; i < HWORDS; i += 1024) dst[i] = sh[i];
}

__global__ void __launch_bounds__(1024) k_threshlo() {
    const int b = blockIdx.x;
    if (((volatile int*)g_mode)[b] != 0) return;
    extern __shared__ unsigned merged[];
    __shared__ unsigned partial[1024];
    __shared__ unsigned coarse[256];
    __shared__ int sel;
    __shared__ unsigned cumsh;
    const int t = threadIdx.x;
    const unsigned* p = g_histp + ((size_t)b * HSLICES << 15);
    unsigned csum = 0;
    #pragma unroll
    for (int k = 0; k < 32; k++) {
        int w = t * 32 + k;
        unsigned m = p[w] + p[HWORDS + w] + p[2 * HWORDS + w] + p[3 * HWORDS + w];
        merged[w] = m;
        csum += (m & 0xFFFFu) + (m >> 16);
    }
    partial[t] = csum;
    __syncthreads();
    if (t < 256)
        coarse[t] = partial[4 * t] + partial[4 * t + 1] +
                    partial[4 * t + 2] + partial[4 * t + 3];
    __syncthreads();
    if (t == 0) {
        sel = -1;
        unsigned cum = 0;
        unsigned h0 = merged[0] & 0xFFFFu;
        for (int c = 255; c >= 0; c--) {
            unsigned cc = coarse[c] - (c == 0 ? h0 : 0u);
            if (cum + cc >= TOPK) { sel = c; cumsh = cum; break; }
            cum += cc;
        }
        if (sel < 0) g_thr[b] = 1;
        else {
            unsigned cum2 = cumsh;
            int T = 1;
            int lo = (sel == 0) ? 1 : 0;
            for (int fb = 255; fb >= lo; fb--) {
                int bin = (sel << 8) + fb;
                unsigned m = merged[bin >> 1];
                unsigned cc = (bin & 1) ? (m >> 16) : (m & 0xFFFFu);
                cum2 += cc;
                if (cum2 >= TOPK) { T = bin; break; }
            }
            g_thr[b] = T;
        }
    }
}

// ---------------- kernel 3: collect candidates ------------------------------
__global__ void k_collect(const float4* __restrict__ s4) {
    const int b = blockIdx.y;
    const int perb4 = NCF / 4;
    const unsigned T = (unsigned)g_thr[b];
    const int mode = g_mode[b];
    const float4* src = s4 + (size_t)b * perb4;
    const int stride = gridDim.x * blockDim.x;
    int i = blockIdx.x * blockDim.x + threadIdx.x;
    #pragma unroll 4
    for (; i < perb4; i += stride) {
        float4 v = src[i];
        float vv[4] = {v.x, v.y, v.z, v.w};
        #pragma unroll
        for (int q = 0; q < 4; q++) {
            float s = vv[q];
            bool acc = mode ? (s > CLO && binhi(s) >= T) : (binlo(s) >= T);
            if (acc) {
                int p = atomicAdd(&g_cnt[b], 1);
                if (p < CAP) {
                    unsigned idx = (unsigned)(i * 4 + q);
                    unsigned key = __float_as_uint(s);
                    g_cand[b * CAP + p] =
                        ((unsigned long long)key << 32) | (unsigned long long)(~idx);
                }
            }
        }
    }
}

// ---------------- kernel 4: per-batch bitonic sort (dynamic n) + gather -----
// key u64 = (float_bits << 32) | ~flat_idx, descending ->
// score desc, flat idx ascending on ties (matches lax.top_k stability)
__global__ void __launch_bounds__(1024) k_sort(const float4* __restrict__ boxes) {
    extern __shared__ unsigned long long sm[];
    int b = blockIdx.x;
    int tid = threadIdx.x;
    int cnt = g_cnt[b];
    if (cnt > CAP) cnt = CAP;
    int n2 = 2048;
    while (n2 < cnt) n2 <<= 1;
    for (int i = tid; i < n2; i += 1024)
        sm[i] = (i < cnt) ? g_cand[b * CAP + i] : 0ull;
    __syncthreads();

    for (int k2 = 2; k2 <= n2; k2 <<= 1) {
        for (int j = k2 >> 1; j > 0; j >>= 1) {
            for (int i = tid; i < n2; i += 1024) {
                int ixj = i ^ j;
                if (ixj > i) {
                    unsigned long long a = sm[i], c = sm[ixj];
                    bool desc = ((i & k2) == 0);
                    if (desc ? (a < c) : (a > c)) { sm[i] = c; sm[ixj] = a; }
                }
            }
            __syncthreads();
        }
    }

    unsigned long long kk = sm[tid];
    unsigned keyhi = (unsigned)(kk >> 32);
    float4 bx = make_float4(0.f, 0.f, 0.f, 0.f);
    int cls = 0; float sc = 0.f;
    if (keyhi != 0) {
        unsigned idx = ~(unsigned)(kk & 0xFFFFFFFFull);
        int n = (int)(idx / NCLS);
        cls = (int)(idx % NCLS);
        sc = __uint_as_float(keyhi);
        bx = boxes[b * NN + n];
    }
    g_box[b * TOPK + tid] = bx;
    g_cls[b * TOPK + tid] = cls;
    g_sc [b * TOPK + tid] = sc;
}

// rotate-swizzled mask slot: row i, col-word w (conflict-free store AND load)
__device__ __forceinline__ int midx(int i, int w) {
    return (i << 5) + ((w + i) & 31);
}

// ---------------- kernel 5: fused mask build + sequential sweep + output ----
__global__ void __launch_bounds__(1024) k_nms(float* __restrict__ out) {
    extern __shared__ unsigned smask[];              // TOPK*32 words = 128 KB
    __shared__ float sy1[TOPK], sx1[TOPK], sy2[TOPK], sx2[TOPK], sa[TOPK];
    __shared__ int   scl[TOPK];
    __shared__ unsigned keepw[32];
    __shared__ int kpref[33];
    int b = blockIdx.x;
    int t = threadIdx.x;

    float sc = g_sc[b * TOPK + t];
    {
        float4 bx = g_box[b * TOPK + t];
        int c = g_cls[b * TOPK + t];
        float off = (float)c * 4096.0f;              // exact in fp32
        float y1 = __fadd_rn(bx.x, off);
        float x1 = __fadd_rn(bx.y, off);
        float y2 = __fadd_rn(bx.z, off);
        float x2 = __fadd_rn(bx.w, off);
        sy1[t] = y1; sx1[t] = x1; sy2[t] = y2; sx2[t] = x2; scl[t] = c;
        sa[t] = __fmul_rn(__fadd_rn(__fsub_rn(x2, x1), 1.0f),
                          __fadd_rn(__fsub_rn(y2, y1), 1.0f));
    }
    unsigned bal = __ballot_sync(0xffffffff, sc > THRS);   // keep0
    if ((t & 31) == 0) keepw[t >> 5] = bal;
    __syncthreads();

    {
        float iy1 = sy1[t], ix1 = sx1[t], iy2 = sy2[t], ix2 = sx2[t], ia = sa[t];
        int ic = scl[t];
        #pragma unroll 1
        for (int w = 0; w < 32; w++) {
            unsigned bits = 0;
            int jb = w << 5;
            if (jb + 31 > t) {
                #pragma unroll 4
                for (int jj = 0; jj < 32; jj++) {
                    int j = jb + jj;
                    if (j > t && scl[j] == ic) {
                        float yy1 = fmaxf(iy1, sy1[j]);
                        float xx1 = fmaxf(ix1, sx1[j]);
                        float yy2 = fminf(iy2, sy2[j]);
                        float xx2 = fminf(ix2, sx2[j]);
                        float ww = fmaxf(0.0f, __fadd_rn(__fsub_rn(xx2, xx1), 1.0f));
                        float hh = fmaxf(0.0f, __fadd_rn(__fsub_rn(yy2, yy1), 1.0f));
                        float inter = __fmul_rn(ww, hh);
                        float iou = __fdiv_rn(inter,
                                     __fsub_rn(__fadd_rn(ia, sa[j]), inter));
                        if (iou > IOUT) bits |= (1u << jj);
                    }
                }
            }
            smask[midx(t, w)] = bits;
        }
    }
    __syncthreads();

    if (t < 32) {
        unsigned my = keepw[t];
        for (int i = 0; i < TOPK; i++) {
            unsigned kw = __shfl_sync(0xffffffff, my, i >> 5);
            if ((kw >> (i & 31)) & 1u)
                my &= ~smask[midx(i, t)];
        }
        keepw[t] = my;
        int p = __popc(my);
        int x = p;
        #pragma unroll
        for (int o = 1; o < 32; o <<= 1) {
            int y = __shfl_up_sync(0xffffffff, x, o);
            if (t >= o) x += y;
        }
        kpref[t] = x - p;
        if (t == 31) kpref[32] = x;
    }
    __syncthreads();

    int w = t >> 5, l = t & 31;
    unsigned kw = keepw[w];
    bool kept = (kw >> l) & 1u;
    unsigned lowm = (l == 0) ? 0u : ((1u << l) - 1u);
    int TKall = kpref[32];

    int slot = -1;
    float oscore = 0.0f;
    if (kept) {
        int kr = kpref[w] + __popc(kw & lowm);
        if (kr < NDET) { slot = kr; oscore = sc; }
    } else {
        int sr = (w << 5) - kpref[w] + __popc((~kw) & lowm);
        int s2 = TKall + sr;
        if (s2 < NDET) { slot = s2; oscore = 0.0f; }
    }

    if (slot >= 0) {
        float4 bx = g_box[b * TOPK + t];
        float* ob = out + ((size_t)b * NDET + slot) * 4;
        ob[0] = bx.x; ob[1] = bx.y; ob[2] = bx.z; ob[3] = bx.w;
        out[NB * NDET * 4 + b * NDET + slot] = oscore;
        out[NB * NDET * 5 + b * NDET + slot] = (float)g_cls[b * TOPK + t];
    }
    if (t == 0)
        out[NB * NDET * 6 + b] = (float)(TKall < NDET ? TKall : NDET);
}

// ---------------- launch ----------------------------------------------------
extern "C" void kernel_launch(void* const* d_in, const int* in_sizes, int n_in,
                              void* d_out, int out_size) {
    const float* boxes  = (const float*)d_in[0];
    const float* scores = (const float*)d_in[1];
    if (n_in >= 2 && in_sizes[0] > in_sizes[1]) {
        boxes  = (const float*)d_in[1];
        scores = (const float*)d_in[0];
    }
    float* out = (float*)d_out;

    cudaFuncSetAttribute(k_hist,     cudaFuncAttributeMaxDynamicSharedMemorySize, HWORDS * 4);
    cudaFuncSetAttribute(k_histlo,   cudaFuncAttributeMaxDynamicSharedMemorySize, HWORDS * 4);
    cudaFuncSetAttribute(k_threshlo, cudaFuncAttributeMaxDynamicSharedMemorySize, HWORDS * 4);
    cudaFuncSetAttribute(k_sort,     cudaFuncAttributeMaxDynamicSharedMemorySize, CAP * 8);
    cudaFuncSetAttribute(k_nms,      cudaFuncAttributeMaxDynamicSharedMemorySize, TOPK * 32 * 4);

    k_hist    <<<dim3(HSLICES, NB), 1024, HWORDS * 4>>>((const float4*)scores);
    k_thresh  <<<NB, 256>>>();
    k_histlo  <<<dim3(HSLICES, NB), 1024, HWORDS * 4>>>((const float4*)scores);
    k_threshlo<<<NB, 1024, HWORDS * 4>>>();
    k_collect <<<dim3(164, NB), 256>>>((const float4*)scores);
    k_sort    <<<NB, 1024, CAP * 8>>>((const float4*)boxes);
    k_nms     <<<NB, 1024, TOPK * 32 * 4>>>(out);
}

// round 5
// speedup vs baseline: 7.0813x; 2.6013x over previous
#include <cuda_runtime.h>
#include <cuda_bf16.h>

// Problem constants
#define NB   32
#define NN   8400
#define NCLS 80
#define NCF  (NN * NCLS)       // 672000 scores per batch
#define TOPK 1024
#define CAP  8192
#define NDET 300
#define THRS 0.001f
#define IOUT 0.7f

#define CLO    0.96875f        // high-region lower bound (31/32, exact fp32)
#define HSCAL  1048576.0f      // 2^20: (s-CLO)*2^20 in (0, 32768]
#define NBINS  32768
#define HWORDS 16384           // bins packed as u16 pairs
#define HSLICES 8
#define NSEG   (HSLICES * 32)  // per-warp private segments per batch = 256
#define SEGCAP 256             // entries per segment (expected ~82)

// ---------------- scratch (device globals; no allocation allowed) ----------
__device__ unsigned int        g_histp[NB * HSLICES * HWORDS];  // 16 MB
__device__ unsigned int        g_coarse[NB * 256];
__device__ int                 g_thr[NB];
__device__ int                 g_mode[NB];
__device__ int                 g_usehi[NB];
__device__ int                 g_segcnt[NB * NSEG];
__device__ unsigned long long  g_hi[NB * NSEG * SEGCAP];        // 16 MB
__device__ int                 g_cnt[NB];
__device__ unsigned long long  g_cand[NB * CAP];
__device__ float4              g_box[NB * TOPK];
__device__ float               g_sc [NB * TOPK];
__device__ int                 g_cls[NB * TOPK];

// high-region bin (valid only for s > CLO): monotonic in s, 0..32767
__device__ __forceinline__ unsigned binhi(float s) {
    unsigned b = (unsigned)(__fmul_rn(__fsub_rn(s, CLO), HSCAL));
    return b > (NBINS - 1) ? (NBINS - 1) : b;
}
// full-range bin (fallback): 0 for masked scores, else 1..32767 monotonic
__device__ __forceinline__ unsigned binlo2(float s) {
    if (!(s > THRS)) return 0u;
    unsigned b = (unsigned)(s * 32768.0f);
    return b > (NBINS - 1) ? (NBINS - 1) : b;
}

// ---------------- kernel 1: fused scan (hist + hi-candidate capture) --------
// grid (HSLICES, NB), 1024 threads, 64 KB smem. Per-warp private candidate
// segments -> zero global atomics; ~21k smem atomics per batch total.
__global__ void __launch_bounds__(1024) k_scan(const float4* __restrict__ s4) {
    extern __shared__ unsigned sh[];
    const int b = blockIdx.y, s = blockIdx.x, t = threadIdx.x;
    const int warp = t >> 5, lane = t & 31;
    for (int i = t; i < HWORDS; i += 1024) sh[i] = 0;
    __syncthreads();

    const int perb4 = NCF / 4;                 // 168000
    const int slice = perb4 / HSLICES;         // 21000
    const int ITERS = (slice + 1023) / 1024;   // 21
    const float4* src = s4 + (size_t)b * perb4 + (size_t)s * slice;
    const int eltbase = s * slice;

    const int seg = s * 32 + warp;
    unsigned long long* mybuf = g_hi + ((size_t)(b * NSEG + seg)) * SEGCAP;
    int wcnt = 0;

    for (int it = 0; it < ITERS; it++) {
        int i = it * 1024 + t;
        float4 v = (i < slice) ? src[i] : make_float4(0.f, 0.f, 0.f, 0.f);
        float comp[4] = {v.x, v.y, v.z, v.w};
        #pragma unroll
        for (int q = 0; q < 4; q++) {
            float sv = comp[q];
            bool pred = (sv > CLO);
            if (pred) {
                unsigned k = binhi(sv);
                atomicAdd(&sh[k >> 1], 1u << ((k & 1) * 16));
            }
            unsigned msk = __ballot_sync(0xffffffffu, pred);
            if (msk) {
                if (pred) {
                    int p = wcnt + __popc(msk & ((1u << lane) - 1u));
                    if (p < SEGCAP) {
                        unsigned idx = (unsigned)((eltbase + i) * 4 + q);
                        mybuf[p] = ((unsigned long long)__float_as_uint(sv) << 32)
                                 | (unsigned long long)(~idx);
                    }
                }
                wcnt += __popc(msk);
            }
        }
    }
    if (lane == 0) g_segcnt[b * NSEG + seg] = wcnt;   // raw (overflow detectable)

    __syncthreads();
    if (t < 256) {
        unsigned sum = 0;
        #pragma unroll 8
        for (int k = 0; k < 64; k++) {
            unsigned m = sh[t * 64 + k];
            sum += (m & 0xFFFFu) + (m >> 16);
        }
        if (sum) atomicAdd(&g_coarse[b * 256 + t], sum);
    }
    unsigned* dst = g_histp + (size_t)(b * HSLICES + s) * HWORDS;
    for (int i = t; i < HWORDS; i += 1024) dst[i] = sh[i];
}

// ---------------- kernel 2: threshold from coarse + one fine chunk ----------
__global__ void __launch_bounds__(256) k_thresh() {
    __shared__ unsigned co[256];
    __shared__ unsigned fine2[128];
    __shared__ int sel;
    __shared__ unsigned cumsh;
    __shared__ int ovf;
    const int b = blockIdx.x, t = threadIdx.x;
    if (t == 0) { g_cnt[b] = 0; ovf = 0; }
    co[t] = g_coarse[b * 256 + t];
    __syncthreads();
    if (g_segcnt[b * NSEG + t] > SEGCAP) atomicOr(&ovf, 1);

    if (t == 0) {
        sel = -1;
        unsigned cum = 0;
        for (int c = 255; c >= 0; c--) {
            if (cum + co[c] >= TOPK) { sel = c; cumsh = cum; break; }
            cum += co[c];
        }
        if (sel < 0) { g_mode[b] = 0; g_usehi[b] = 0; }
    }
    __syncthreads();
    int c = sel;
    if (c >= 0) {
        if (t < 64) {
            const unsigned* p = g_histp + (size_t)b * HSLICES * HWORDS + c * 64 + t;
            unsigned m = 0;
            #pragma unroll
            for (int sd = 0; sd < HSLICES; sd++) m += p[(size_t)sd * HWORDS];
            fine2[2 * t]     = m & 0xFFFFu;
            fine2[2 * t + 1] = m >> 16;
        }
        __syncthreads();
        if (t == 0) {
            unsigned cum = cumsh;
            int T = 0;
            for (int fb = 127; fb >= 0; fb--) {
                cum += fine2[fb];
                if (cum >= TOPK) { T = (c << 7) + fb; break; }
            }
            g_thr[b] = T;
            g_mode[b] = 1;
            g_usehi[b] = ovf ? 0 : 1;
        }
    }
    g_coarse[b * 256 + t] = 0;   // clean for next replay
}

// ---------------- kernel 3: gated full-range threshold fallback (cold) ------
__global__ void __launch_bounds__(1024) k_fallbackT(const float4* __restrict__ s4) {
    const int b = blockIdx.x;
    if (((volatile int*)g_mode)[b] != 0) return;
    extern __shared__ unsigned sh[];
    __shared__ unsigned co[256];
    const int t = threadIdx.x;
    for (int i = t; i < HWORDS; i += 1024) sh[i] = 0;
    __syncthreads();
    const int perb4 = NCF / 4;
    const float4* src = s4 + (size_t)b * perb4;
    for (int i = t; i < perb4; i += 1024) {
        float4 v = src[i];
        float comp[4] = {v.x, v.y, v.z, v.w};
        #pragma unroll
        for (int q = 0; q < 4; q++) {
            unsigned k = binlo2(comp[q]);
            atomicAdd(&sh[k >> 1], 1u << ((k & 1) * 16));
        }
    }
    __syncthreads();
    if (t < 256) {
        unsigned sum = 0;
        for (int k = 0; k < 64; k++) {
            unsigned m = sh[t * 64 + k];
            sum += (m & 0xFFFFu) + (m >> 16);
        }
        co[t] = sum;
    }
    __syncthreads();
    if (t == 0) {
        unsigned h0 = sh[0] & 0xFFFFu;
        int sel = -1; unsigned cum = 0, cums = 0;
        for (int c = 255; c >= 0; c--) {
            unsigned cc = co[c] - (c == 0 ? h0 : 0u);
            if (cum + cc >= TOPK) { sel = c; cums = cum; break; }
            cum += cc;
        }
        int T = 1;
        if (sel >= 0) {
            unsigned cum2 = cums;
            int lo = (sel == 0) ? 1 : 0;
            for (int fb = 127; fb >= lo; fb--) {
                int bin = (sel << 7) + fb;
                unsigned m = sh[bin >> 1];
                unsigned cc = (bin & 1) ? (m >> 16) : (m & 0xFFFFu);
                cum2 += cc;
                if (cum2 >= TOPK) { T = bin; break; }
            }
        }
        g_thr[b] = T;
    }
}

// ---------------- kernel 4: filter candidates >= T --------------------------
__global__ void k_filter(const float4* __restrict__ s4) {
    const int b = blockIdx.y;
    const unsigned T = (unsigned)g_thr[b];
    const int stride = gridDim.x * blockDim.x;
    int tid = blockIdx.x * blockDim.x + threadIdx.x;
    if (g_usehi[b]) {
        // hot path: scan private segments (~21k entries, 170 KB)
        for (int slot = tid; slot < NSEG * SEGCAP; slot += stride) {
            int seg = slot >> 8, off = slot & (SEGCAP - 1);
            if (off < g_segcnt[b * NSEG + seg]) {
                unsigned long long kk = g_hi[((size_t)(b * NSEG + seg)) * SEGCAP + off];
                float sv = __uint_as_float((unsigned)(kk >> 32));
                if (binhi(sv) >= T) {
                    int p = atomicAdd(&g_cnt[b], 1);
                    if (p < CAP) g_cand[b * CAP + p] = kk;
                }
            }
        }
    } else {
        // cold path: full rescan
        const int mode = g_mode[b];
        const int perb4 = NCF / 4;
        const float4* src = s4 + (size_t)b * perb4;
        for (int i = tid; i < perb4; i += stride) {
            float4 v = src[i];
            float comp[4] = {v.x, v.y, v.z, v.w};
            #pragma unroll
            for (int q = 0; q < 4; q++) {
                float sv = comp[q];
                bool acc = mode ? (sv > CLO && binhi(sv) >= T) : (binlo2(sv) >= T);
                if (acc) {
                    int p = atomicAdd(&g_cnt[b], 1);
                    if (p < CAP) {
                        unsigned idx = (unsigned)(i * 4 + q);
                        g_cand[b * CAP + p] =
                            ((unsigned long long)__float_as_uint(sv) << 32)
                            | (unsigned long long)(~idx);
                    }
                }
            }
        }
    }
}

// ---------------- kernel 5: per-batch bitonic sort (dynamic n) + gather -----
// key u64 = (float_bits << 32) | ~flat_idx, descending ->
// score desc, flat idx ascending on ties (matches lax.top_k stability)
__global__ void __launch_bounds__(1024) k_sort(const float4* __restrict__ boxes) {
    extern __shared__ unsigned long long sm[];
    int b = blockIdx.x;
    int tid = threadIdx.x;
    int cnt = g_cnt[b];
    if (cnt > CAP) cnt = CAP;
    int n2 = 2048;
    while (n2 < cnt) n2 <<= 1;
    for (int i = tid; i < n2; i += 1024)
        sm[i] = (i < cnt) ? g_cand[b * CAP + i] : 0ull;
    __syncthreads();

    for (int k2 = 2; k2 <= n2; k2 <<= 1) {
        for (int j = k2 >> 1; j > 0; j >>= 1) {
            for (int i = tid; i < n2; i += 1024) {
                int ixj = i ^ j;
                if (ixj > i) {
                    unsigned long long a = sm[i], c = sm[ixj];
                    bool desc = ((i & k2) == 0);
                    if (desc ? (a < c) : (a > c)) { sm[i] = c; sm[ixj] = a; }
                }
            }
            __syncthreads();
        }
    }

    unsigned long long kk = sm[tid];
    unsigned keyhi = (unsigned)(kk >> 32);
    float4 bx = make_float4(0.f, 0.f, 0.f, 0.f);
    int cls = 0; float sc = 0.f;
    if (keyhi != 0) {
        unsigned idx = ~(unsigned)(kk & 0xFFFFFFFFull);
        int n = (int)(idx / NCLS);
        cls = (int)(idx % NCLS);
        sc = __uint_as_float(keyhi);
        bx = boxes[b * NN + n];
    }
    g_box[b * TOPK + tid] = bx;
    g_cls[b * TOPK + tid] = cls;
    g_sc [b * TOPK + tid] = sc;
}

// ---------------- kernel 6: per-class greedy NMS + output -------------------
// Cross-class IoU is exactly 0 (class offset gap >= 3455 after fp32 rounding),
// so global greedy == independent per-class greedy in global-rank order.
// IoU ops identical to reference: offset coords, a[i]+a[j] with suppressor
// first, strict > 0.7, __f*_rn arithmetic.
__global__ void __launch_bounds__(1024) k_nms(float* __restrict__ out) {
    __shared__ float sy1[TOPK], sx1[TOPK], sy2[TOPK], sx2[TOPK], sa[TOPK];
    __shared__ unsigned short wcount[NCLS * 32];
    __shared__ unsigned short wbase [NCLS * 32];
    __shared__ unsigned short ctot[NCLS];
    __shared__ unsigned short cstart[NCLS + 1];
    __shared__ unsigned short list[TOPK];
    __shared__ unsigned char  skept[TOPK];
    __shared__ unsigned kw[32];
    __shared__ int kpref[33];

    int b = blockIdx.x;
    int t = threadIdx.x;
    int warp = t >> 5, lane = t & 31;

    float sc = g_sc[b * TOPK + t];
    int c = g_cls[b * TOPK + t];
    {
        float4 bx = g_box[b * TOPK + t];
        float off = (float)c * 4096.0f;              // exact in fp32
        float y1 = __fadd_rn(bx.x, off);
        float x1 = __fadd_rn(bx.y, off);
        float y2 = __fadd_rn(bx.z, off);
        float x2 = __fadd_rn(bx.w, off);
        sy1[t] = y1; sx1[t] = x1; sy2[t] = y2; sx2[t] = x2;
        sa[t] = __fmul_rn(__fadd_rn(__fsub_rn(x2, x1), 1.0f),
                          __fadd_rn(__fsub_rn(y2, y1), 1.0f));
    }
    bool valid = (sc > THRS);
    unsigned bal = __ballot_sync(0xffffffff, valid);
    if (lane == 0) kw[warp] = bal;
    for (int i = t; i < NCLS * 32; i += 1024) wcount[i] = 0;
    skept[t] = 1;
    __syncthreads();

    // stable per-class list build
    int cc = valid ? c : 0x7FFF;
    unsigned mm = __match_any_sync(0xffffffffu, cc);
    int rank = __popc(mm & ((1u << lane) - 1u));
    int ldr = __ffs(mm) - 1;
    if (valid && lane == ldr) wcount[cc * 32 + warp] = (unsigned short)__popc(mm);
    __syncthreads();
    if (t < NCLS) {
        int run = 0;
        for (int w = 0; w < 32; w++) {
            int v = wcount[t * 32 + w];
            wbase[t * 32 + w] = (unsigned short)run;
            run += v;
        }
        ctot[t] = (unsigned short)run;
    }
    __syncthreads();
    if (t == 0) {
        int s = 0;
        for (int c2 = 0; c2 < NCLS; c2++) { cstart[c2] = (unsigned short)s; s += ctot[c2]; }
        cstart[NCLS] = (unsigned short)s;
    }
    __syncthreads();
    if (valid) list[cstart[cc] + wbase[cc * 32 + warp] + rank] = (unsigned short)t;
    __syncthreads();

    // per-class greedy (one warp per class, strided)
    for (int c2 = warp; c2 < NCLS; c2 += 32) {
        int m = ctot[c2];
        if (m < 2) continue;
        int base = cstart[c2];
        if (m <= 32) {
            int tj = 0; bool kept = false;
            float jy1 = 0, jx1 = 0, jy2 = 0, jx2 = 0, ja = 0;
            if (lane < m) {
                tj = list[base + lane];
                jy1 = sy1[tj]; jx1 = sx1[tj]; jy2 = sy2[tj]; jx2 = sx2[tj]; ja = sa[tj];
                kept = true;
            }
            for (int i = 0; i < m - 1; i++) {
                unsigned alive = __ballot_sync(0xffffffffu, kept);
                if (!((alive >> i) & 1u)) continue;
                int ti = list[base + i];                       // LDS broadcast
                float iy1 = sy1[ti], ix1 = sx1[ti], iy2 = sy2[ti], ix2 = sx2[ti], ia = sa[ti];
                if (lane > i && kept) {
                    float yy1 = fmaxf(iy1, jy1);
                    float xx1 = fmaxf(ix1, jx1);
                    float yy2 = fminf(iy2, jy2);
                    float xx2 = fminf(ix2, jx2);
                    float ww = fmaxf(0.0f, __fadd_rn(__fsub_rn(xx2, xx1), 1.0f));
                    float hh = fmaxf(0.0f, __fadd_rn(__fsub_rn(yy2, yy1), 1.0f));
                    float inter = __fmul_rn(ww, hh);
                    float iou = __fdiv_rn(inter, __fsub_rn(__fadd_rn(ia, ja), inter));
                    if (iou > IOUT) kept = false;
                }
            }
            if (lane < m && !kept) atomicAnd(&kw[tj >> 5], ~(1u << (tj & 31)));
        } else {
            for (int i = 0; i < m - 1; i++) {
                __syncwarp();
                if (!skept[base + i]) continue;
                int ti = list[base + i];
                float iy1 = sy1[ti], ix1 = sx1[ti], iy2 = sy2[ti], ix2 = sx2[ti], ia = sa[ti];
                for (int k = i + 1 + lane; k < m; k += 32) {
                    if (skept[base + k]) {
                        int tk = list[base + k];
                        float yy1 = fmaxf(iy1, sy1[tk]);
                        float xx1 = fmaxf(ix1, sx1[tk]);
                        float yy2 = fminf(iy2, sy2[tk]);
                        float xx2 = fminf(ix2, sx2[tk]);
                        float ww = fmaxf(0.0f, __fadd_rn(__fsub_rn(xx2, xx1), 1.0f));
                        float hh = fmaxf(0.0f, __fadd_rn(__fsub_rn(yy2, yy1), 1.0f));
                        float inter = __fmul_rn(ww, hh);
                        float iou = __fdiv_rn(inter, __fsub_rn(__fadd_rn(ia, sa[tk]), inter));
                        if (iou > IOUT) skept[base + k] = 0;
                    }
                }
            }
            __syncwarp();
            for (int k = lane; k < m; k += 32)
                if (!skept[base + k]) {
                    int tk = list[base + k];
                    atomicAnd(&kw[tk >> 5], ~(1u << (tk & 31)));
                }
        }
    }
    __syncthreads();

    // ranking (identical to prior rounds)
    if (t < 32) {
        unsigned my = kw[t];
        int p = __popc(my);
        int x = p;
        #pragma unroll
        for (int o = 1; o < 32; o <<= 1) {
            int y = __shfl_up_sync(0xffffffff, x, o);
            if (t >= o) x += y;
        }
        kpref[t] = x - p;
        if (t == 31) kpref[32] = x;
    }
    __syncthreads();

    int w = t >> 5, l = t & 31;
    unsigned kwv = kw[w];
    bool kept = (kwv >> l) & 1u;
    unsigned lowm = (l == 0) ? 0u : ((1u << l) - 1u);
    int TKall = kpref[32];

    int slot = -1;
    float oscore = 0.0f;
    if (kept) {
        int kr = kpref[w] + __popc(kwv & lowm);
        if (kr < NDET) { slot = kr; oscore = sc; }
    } else {
        int sr = (w << 5) - kpref[w] + __popc((~kwv) & lowm);
        int s2 = TKall + sr;
        if (s2 < NDET) { slot = s2; oscore = 0.0f; }
    }

    // output layout (float32): boxes[32,300,4] | scores[32,300] | labels[32,300] | n_valid[32,1]
    if (slot >= 0) {
        float4 bx = g_box[b * TOPK + t];
        float* ob = out + ((size_t)b * NDET + slot) * 4;
        ob[0] = bx.x; ob[1] = bx.y; ob[2] = bx.z; ob[3] = bx.w;
        out[NB * NDET * 4 + b * NDET + slot] = oscore;
        out[NB * NDET * 5 + b * NDET + slot] = (float)c;
    }
    if (t == 0)
        out[NB * NDET * 6 + b] = (float)(TKall < NDET ? TKall : NDET);
}

// ---------------- launch ----------------------------------------------------
extern "C" void kernel_launch(void* const* d_in, const int* in_sizes, int n_in,
                              void* d_out, int out_size) {
    const float* boxes  = (const float*)d_in[0];
    const float* scores = (const float*)d_in[1];
    if (n_in >= 2 && in_sizes[0] > in_sizes[1]) {
        boxes  = (const float*)d_in[1];
        scores = (const float*)d_in[0];
    }
    float* out = (float*)d_out;

    cudaFuncSetAttribute(k_scan,      cudaFuncAttributeMaxDynamicSharedMemorySize, HWORDS * 4);
    cudaFuncSetAttribute(k_fallbackT, cudaFuncAttributeMaxDynamicSharedMemorySize, HWORDS * 4);
    cudaFuncSetAttribute(k_sort,      cudaFuncAttributeMaxDynamicSharedMemorySize, CAP * 8);

    k_scan     <<<dim3(HSLICES, NB), 1024, HWORDS * 4>>>((const float4*)scores);
    k_thresh   <<<NB, 256>>>();
    k_fallbackT<<<NB, 1024, HWORDS * 4>>>((const float4*)scores);
    k_filter   <<<dim3(16, NB), 256>>>((const float4*)scores);
    k_sort     <<<NB, 1024, CAP * 8>>>((const float4*)boxes);
    k_nms      <<<NB, 1024>>>(out);
}